// round 8
// baseline (speedup 1.0000x reference)
#include <cuda_runtime.h>
#include <cuda_bf16.h>

#define GAMA 1.0f
#define ROW_L 1024
#define THREADS 256
#define NBLOCKS 128
#define NGROUPS 8
#define GSIZE   (NBLOCKS / NGROUPS)   // 16

// Hierarchical self-resetting accumulators. 256B stride keeps each slot in a
// distinct L2 line (and avoids the bit-7 hash pairing). Zero at module load;
// the final block restores zeros each replay.
struct alignas(256) Slot { float v; unsigned tk; };
__device__ Slot     g_slot[NGROUPS];   // zero-initialized
__device__ unsigned g_final = 0u;

__device__ __forceinline__ float fast_sigmoid(float x) {
    float t;
    asm("tanh.approx.f32 %0, %1;" : "=f"(t) : "f"(x * 0.5f));
    return fmaf(0.5f, t, 0.5f);
}

// One block per row, one float4+int4 per thread (best measured shape).
// p = sigmoid(x) in [0,1], GAMA=1 => relu(1 + p_i - p_j) is identity on all
// neg-pos pairs: row loss = c0*c1*GAMA + c1*S0 - c0*S1, S0 = S - S1, c0 = L - c1.
__global__ __launch_bounds__(THREADS) void prl_kernel(
    const float4* __restrict__ logit4,
    const int4*   __restrict__ label4,
    float* __restrict__ out)
{
    const int t = threadIdx.x;
    const int base = blockIdx.x * (ROW_L / 4);

    const float4 x = logit4[base + t];
    const int4   y = label4[base + t];

    const float p0 = fast_sigmoid(x.x);
    const float p1 = fast_sigmoid(x.y);
    const float p2 = fast_sigmoid(x.z);
    const float p3 = fast_sigmoid(x.w);

    const float fy0 = (float)y.x, fy1 = (float)y.y;
    const float fy2 = (float)y.z, fy3 = (float)y.w;

    float S  = (p0 + p1) + (p2 + p3);
    float c1 = (fy0 + fy1) + (fy2 + fy3);
    float s1 = fmaf(p0, fy0, fmaf(p1, fy1, fmaf(p2, fy2, p3 * fy3)));

    #pragma unroll
    for (int off = 16; off > 0; off >>= 1) {
        S  += __shfl_down_sync(0xFFFFFFFFu, S,  off);
        c1 += __shfl_down_sync(0xFFFFFFFFu, c1, off);
        s1 += __shfl_down_sync(0xFFFFFFFFu, s1, off);
    }

    __shared__ float shS[8], shC[8], sh1[8];
    const int wid = t >> 5;
    const int lid = t & 31;
    if (lid == 0) { shS[wid] = S; shC[wid] = c1; sh1[wid] = s1; }
    __syncthreads();

    if (wid == 0) {
        S  = (lid < 8) ? shS[lid] : 0.0f;
        c1 = (lid < 8) ? shC[lid] : 0.0f;
        s1 = (lid < 8) ? sh1[lid] : 0.0f;
        #pragma unroll
        for (int off = 4; off > 0; off >>= 1) {
            S  += __shfl_down_sync(0xFFFFFFFFu, S,  off);
            c1 += __shfl_down_sync(0xFFFFFFFFu, c1, off);
            s1 += __shfl_down_sync(0xFFFFFFFFu, s1, off);
        }
        if (lid == 0) {
            const float c0 = (float)ROW_L - c1;
            const float s0 = S - s1;
            const float loss = fmaf(c0 * c1, GAMA, fmaf(c1, s0, -c0 * s1));

            // Interleaved grouping: blocks finishing simultaneously hit
            // different slots -> max per-address contention = 16, not 128.
            const int grp = blockIdx.x & (NGROUPS - 1);
            Slot* slot = &g_slot[grp];

            // Fire-and-forget relaxed add into the group slot.
            asm volatile("red.global.add.f32 [%0], %1;"
                         :: "l"(&slot->v), "f"(loss) : "memory");
            // Group ticket (acq_rel: release orders our red; acquire pulls in
            // the group's other reds via cumulativity).
            unsigned tk;
            asm volatile("atom.global.acq_rel.gpu.add.u32 %0, [%1], %2;"
                         : "=r"(tk) : "l"(&slot->tk), "r"(1u) : "memory");
            if (tk == GSIZE - 1u) {
                // Final ticket across the 8 group finishers.
                unsigned tg;
                asm volatile("atom.global.acq_rel.gpu.add.u32 %0, [%1], %2;"
                             : "=r"(tg) : "l"(&g_final), "r"(1u) : "memory");
                if (tg == NGROUPS - 1u) {
                    float tot = 0.0f;
                    #pragma unroll
                    for (int g = 0; g < NGROUPS; g++) {
                        tot += g_slot[g].v;
                        g_slot[g].v  = 0.0f;     // reset for next replay
                        g_slot[g].tk = 0u;
                    }
                    g_final = 0u;
                    out[0] = tot;
                }
            }
        }
    }
}

extern "C" void kernel_launch(void* const* d_in, const int* in_sizes, int n_in,
                              void* d_out, int out_size)
{
    const float4* logit4 = (const float4*)d_in[0];
    const int4*   label4 = (const int4*)d_in[1];
    float* out = (float*)d_out;

    prl_kernel<<<NBLOCKS, THREADS>>>(logit4, label4, out);
}

// round 10
// speedup vs baseline: 1.0627x; 1.0627x over previous
#include <cuda_runtime.h>
#include <cuda_bf16.h>

#define GAMA 1.0f
#define ROW_L 1024
#define THREADS 256
#define NBLOCKS 128u

// Self-resetting cross-block accumulators (module-load init = 0; the last
// finishing block publishes and restores the zero state each graph replay).
__device__ float        g_partial = 0.0f;
__device__ unsigned int g_ticket  = 0u;

// One block per row, one float4+int4 per thread (best measured shape, R4).
// p = sigmoid(x) in [0,1], GAMA=1 => relu(1 + p_i - p_j) == 1 + p_i - p_j for
// every neg-pos pair, so: row loss = c0*c1*GAMA + c1*S0 - c0*S1,
// with S0 = S - S1, c0 = L - c1.
__global__ __launch_bounds__(THREADS) void prl_kernel(
    const float4* __restrict__ logit4,
    const int4*   __restrict__ label4,
    float* __restrict__ out)
{
    const int t = threadIdx.x;
    const int base = blockIdx.x * (ROW_L / 4);

    const float4 x = logit4[base + t];
    const int4   y = label4[base + t];

    const float p0 = 1.0f / (1.0f + __expf(-x.x));
    const float p1 = 1.0f / (1.0f + __expf(-x.y));
    const float p2 = 1.0f / (1.0f + __expf(-x.z));
    const float p3 = 1.0f / (1.0f + __expf(-x.w));

    const float fy0 = (float)y.x, fy1 = (float)y.y;
    const float fy2 = (float)y.z, fy3 = (float)y.w;

    float S  = (p0 + p1) + (p2 + p3);                                  // sum p
    float s1 = fmaf(p0, fy0, fmaf(p1, fy1, fmaf(p2, fy2, p3 * fy3))); // sum p|pos
    int   c1i = y.x + y.y + y.z + y.w;                                 // pos count

    // Warp stage: 2 float shuffle chains + 1 integer REDUX (sm_103-legal).
    #pragma unroll
    for (int off = 16; off > 0; off >>= 1) {
        S  += __shfl_down_sync(0xFFFFFFFFu, S,  off);
        s1 += __shfl_down_sync(0xFFFFFFFFu, s1, off);
    }
    c1i = __reduce_add_sync(0xFFFFFFFFu, c1i);

    __shared__ float shS[8], sh1[8], shC[8];
    const int wid = t >> 5;
    const int lid = t & 31;
    if (lid == 0) { shS[wid] = S; sh1[wid] = s1; shC[wid] = (float)c1i; }
    __syncthreads();

    if (wid == 0) {
        S        = (lid < 8) ? shS[lid] : 0.0f;
        s1       = (lid < 8) ? sh1[lid] : 0.0f;
        float c1 = (lid < 8) ? shC[lid] : 0.0f;
        #pragma unroll
        for (int off = 4; off > 0; off >>= 1) {
            S  += __shfl_down_sync(0xFFFFFFFFu, S,  off);
            s1 += __shfl_down_sync(0xFFFFFFFFu, s1, off);
            c1 += __shfl_down_sync(0xFFFFFFFFu, c1, off);
        }
        if (lid == 0) {
            const float c0 = (float)ROW_L - c1;
            const float s0 = S - s1;
            const float loss = fmaf(c0 * c1, GAMA, fmaf(c1, s0, -c0 * s1));
            atomicAdd(&g_partial, loss);
            __threadfence();
            const unsigned tk = atomicAdd(&g_ticket, 1u);
            if (tk == NBLOCKS - 1u) {
                out[0]   = atomicExch(&g_partial, 0.0f);  // publish + reset
                g_ticket = 0u;
            }
        }
    }
}

extern "C" void kernel_launch(void* const* d_in, const int* in_sizes, int n_in,
                              void* d_out, int out_size)
{
    const float4* logit4 = (const float4*)d_in[0];
    const int4*   label4 = (const int4*)d_in[1];
    float* out = (float*)d_out;

    prl_kernel<<<NBLOCKS, THREADS>>>(logit4, label4, out);
}

// round 11
// speedup vs baseline: 1.3092x; 1.2319x over previous
#include <cuda_runtime.h>
#include <cuda_bf16.h>

#define GAMA 1.0f
#define ROW_L 1024
#define THREADS 256

// Self-resetting cross-block accumulator (module-load init = 0; the last
// finishing block writes the result and restores the zero state, so every
// graph replay sees clean scratch).
__device__ float        g_partial = 0.0f;
__device__ unsigned int g_ticket  = 0u;

// One block per row (L=1024, 256 threads -> exactly one float4 + one int4 per
// thread). Closed form: p = sigmoid(x) in [0,1], GAMA=1 => the ReLU is always
// identity for neg-pos pairs, so
//   row loss = c0*c1*GAMA + c1*S0 - c0*S1,  S0 = S - S1, c0 = L - c1.
__global__ __launch_bounds__(THREADS) void prl_kernel(
    const float4* __restrict__ logit4,
    const int4*   __restrict__ label4,
    float* __restrict__ out)
{
    const int b = blockIdx.x;
    const int t = threadIdx.x;
    const int base = b * (ROW_L / 4);

    const float4 x = logit4[base + t];
    const int4   y = label4[base + t];

    const float p0 = 1.0f / (1.0f + __expf(-x.x));
    const float p1 = 1.0f / (1.0f + __expf(-x.y));
    const float p2 = 1.0f / (1.0f + __expf(-x.z));
    const float p3 = 1.0f / (1.0f + __expf(-x.w));

    const float fy0 = (float)y.x, fy1 = (float)y.y;
    const float fy2 = (float)y.z, fy3 = (float)y.w;

    float S  = (p0 + p1) + (p2 + p3);                 // sum of all p
    float c1 = (fy0 + fy1) + (fy2 + fy3);             // positive count
    float s1 = fmaf(p0, fy0, fmaf(p1, fy1, fmaf(p2, fy2, p3 * fy3)));  // sum p over positives

    // warp reduce 3 values
    #pragma unroll
    for (int off = 16; off > 0; off >>= 1) {
        S  += __shfl_down_sync(0xFFFFFFFFu, S,  off);
        c1 += __shfl_down_sync(0xFFFFFFFFu, c1, off);
        s1 += __shfl_down_sync(0xFFFFFFFFu, s1, off);
    }

    __shared__ float shS[8], shC[8], sh1[8];
    const int wid = t >> 5;
    const int lid = t & 31;
    if (lid == 0) { shS[wid] = S; shC[wid] = c1; sh1[wid] = s1; }
    __syncthreads();

    if (wid == 0) {
        S  = (lid < (THREADS / 32)) ? shS[lid] : 0.0f;
        c1 = (lid < (THREADS / 32)) ? shC[lid] : 0.0f;
        s1 = (lid < (THREADS / 32)) ? sh1[lid] : 0.0f;
        #pragma unroll
        for (int off = 4; off > 0; off >>= 1) {
            S  += __shfl_down_sync(0xFFFFFFFFu, S,  off);
            c1 += __shfl_down_sync(0xFFFFFFFFu, c1, off);
            s1 += __shfl_down_sync(0xFFFFFFFFu, s1, off);
        }
        if (lid == 0) {
            const float c0 = (float)ROW_L - c1;
            const float s0 = S - s1;
            const float loss = fmaf(c0 * c1, GAMA, fmaf(c1, s0, -c0 * s1));
            atomicAdd(&g_partial, loss);
            __threadfence();
            const unsigned tk = atomicAdd(&g_ticket, 1u);
            if (tk == gridDim.x - 1u) {
                out[0]    = g_partial;   // publish
                g_partial = 0.0f;        // restore clean state for next replay
                g_ticket  = 0u;
            }
        }
    }
}

extern "C" void kernel_launch(void* const* d_in, const int* in_sizes, int n_in,
                              void* d_out, int out_size)
{
    const float4* logit4 = (const float4*)d_in[0];
    const int4*   label4 = (const int4*)d_in[1];
    float* out = (float*)d_out;

    const int B = in_sizes[0] / ROW_L;
    prl_kernel<<<B, THREADS>>>(logit4, label4, out);
}